// round 1
// baseline (speedup 1.0000x reference)
#include <cuda_runtime.h>
#include <math.h>
#include <math_constants.h>

#define N_TOK 16384
#define DIMK  2048
#define NOUT  128   // 64 gate + 64 noise logits

// ---- scratch (no allocations allowed) ----
__device__ float g_logits[2][N_TOK * NOUT];   // split-K partial logits, 16 MB
__device__ int   g_sel[N_TOK * 2];

// ============================================================================
// GEMM: logits[n][e] = sum_d x[n][d] * W[e][d],  W = [w_gate(64); w_noise(64)]
// BM=128, BN=128, BK=16, 256 threads, 8x8 per-thread (4+4 split), split-K=2.
// ============================================================================
__global__ __launch_bounds__(256) void gemm_kernel(
    const float* __restrict__ x,
    const float* __restrict__ wg,
    const float* __restrict__ wn)
{
    __shared__ float As[16][132];   // [k][m], pad 4 keeps float4 alignment
    __shared__ float Bs[16][132];   // [k][e]

    const int tid = threadIdx.x;
    const int tx  = tid & 15;       // 0..15 -> output cols
    const int ty  = tid >> 4;       // 0..15 -> output rows
    const int blockRow = blockIdx.x * 128;
    const int kbase    = blockIdx.y * 1024;
    float* __restrict__ outp = g_logits[blockIdx.y];

    const int lrow = tid >> 2;        // 0..63
    const int lcol = (tid & 3) * 4;   // 0,4,8,12

    float acc[8][8];
    #pragma unroll
    for (int i = 0; i < 8; i++)
        #pragma unroll
        for (int j = 0; j < 8; j++) acc[i][j] = 0.f;

    for (int k0 = 0; k0 < 1024; k0 += 16) {
        // load A tile (tokens x K)
        #pragma unroll
        for (int i = 0; i < 2; i++) {
            const int row = lrow + i * 64;
            const float4 v = *(const float4*)(x + (size_t)(blockRow + row) * DIMK + kbase + k0 + lcol);
            As[lcol + 0][row] = v.x;
            As[lcol + 1][row] = v.y;
            As[lcol + 2][row] = v.z;
            As[lcol + 3][row] = v.w;
        }
        // load B tile (128 expert-rows x K), rows 0..63 gate, 64..127 noise
        #pragma unroll
        for (int i = 0; i < 2; i++) {
            const int row = lrow + i * 64;
            const float* wp = (row < 64) ? (wg + (size_t)row * DIMK)
                                         : (wn + (size_t)(row - 64) * DIMK);
            const float4 v = *(const float4*)(wp + kbase + k0 + lcol);
            Bs[lcol + 0][row] = v.x;
            Bs[lcol + 1][row] = v.y;
            Bs[lcol + 2][row] = v.z;
            Bs[lcol + 3][row] = v.w;
        }
        __syncthreads();

        #pragma unroll
        for (int k = 0; k < 16; k++) {
            const float4 a0 = *(const float4*)&As[k][ty * 4];
            const float4 a1 = *(const float4*)&As[k][64 + ty * 4];
            const float4 b0 = *(const float4*)&Bs[k][tx * 4];
            const float4 b1 = *(const float4*)&Bs[k][64 + tx * 4];
            const float a[8] = {a0.x, a0.y, a0.z, a0.w, a1.x, a1.y, a1.z, a1.w};
            const float b[8] = {b0.x, b0.y, b0.z, b0.w, b1.x, b1.y, b1.z, b1.w};
            #pragma unroll
            for (int i = 0; i < 8; i++)
                #pragma unroll
                for (int j = 0; j < 8; j++)
                    acc[i][j] = fmaf(a[i], b[j], acc[i][j]);
        }
        __syncthreads();
    }

    #pragma unroll
    for (int i = 0; i < 8; i++) {
        const int m = (i < 4) ? (ty * 4 + i) : (64 + ty * 4 + (i - 4));
        float4 c0 = make_float4(acc[i][0], acc[i][1], acc[i][2], acc[i][3]);
        float4 c1 = make_float4(acc[i][4], acc[i][5], acc[i][6], acc[i][7]);
        *(float4*)(outp + (size_t)(blockRow + m) * NOUT + tx * 4)      = c0;
        *(float4*)(outp + (size_t)(blockRow + m) * NOUT + 64 + tx * 4) = c1;
    }
}

// ============================================================================
// Routing epilogue: 1 warp per token (64 experts, 2 per lane).
// Output layout (all float32):
//   [0, 32768)                   routing_weights [n][2]
//   [32768, 65536)               selected_experts [n][2] (as float)
//   [65536, 65536+2097152)       expert_mask [e][j][n]
//   [2162688, 3211264)           load [n][64]
// ============================================================================
__global__ __launch_bounds__(256) void route_kernel(
    const float* __restrict__ noise, float* __restrict__ out)
{
    const int n    = (blockIdx.x * blockDim.x + threadIdx.x) >> 5;
    const int lane = threadIdx.x & 31;
    if (n >= N_TOK) return;

    float rl[2], sv[2], sd[2];
    #pragma unroll
    for (int t = 0; t < 2; t++) {
        const int e = lane * 2 + t;
        const float r = g_logits[0][(size_t)n * NOUT + e] + g_logits[1][(size_t)n * NOUT + e];
        const float w = g_logits[0][(size_t)n * NOUT + 64 + e] + g_logits[1][(size_t)n * NOUT + 64 + e];
        // stable softplus = max(w,0) + log1p(exp(-|w|))
        const float sp  = fmaxf(w, 0.f) + log1pf(expf(-fabsf(w)));
        const float sdv = sp + 0.01f;
        rl[t] = r;
        sd[t] = sdv;
        sv[t] = fmaf(noise[(size_t)n * 64 + e], sdv, r);
    }

    // top-3 via 3x warp argmax (ties -> smaller index, matching jax top_k)
    float vtop[3]; int itop[3];
    float cur0 = sv[0], cur1 = sv[1];
    #pragma unroll
    for (int r = 0; r < 3; r++) {
        float bv; int bi;
        if (cur0 >= cur1) { bv = cur0; bi = lane * 2; }
        else              { bv = cur1; bi = lane * 2 + 1; }
        #pragma unroll
        for (int off = 16; off; off >>= 1) {
            const float ov = __shfl_xor_sync(0xffffffffu, bv, off);
            const int   oi = __shfl_xor_sync(0xffffffffu, bi, off);
            if (ov > bv || (ov == bv && oi < bi)) { bv = ov; bi = oi; }
        }
        vtop[r] = bv; itop[r] = bi;
        if ((bi >> 1) == lane) {
            if (bi & 1) cur1 = -CUDART_INF_F; else cur0 = -CUDART_INF_F;
        }
    }

    const float thr2 = vtop[1];  // threshold_if_out
    const float thr3 = vtop[2];  // threshold_if_in

    if (lane == 0) {
        // softmax over top-2 (v0 >= v1); normalization by sum is identity
        const float a  = expf(vtop[1] - vtop[0]);
        const float s  = 1.f + a;
        out[n * 2 + 0] = 1.f / s;
        out[n * 2 + 1] = a / s;
        out[32768 + n * 2 + 0] = (float)itop[0];
        out[32768 + n * 2 + 1] = (float)itop[1];
        g_sel[n * 2 + 0] = itop[0];
        g_sel[n * 2 + 1] = itop[1];
    }

    #pragma unroll
    for (int t = 0; t < 2; t++) {
        const int e = lane * 2 + t;
        const bool  isin = sv[t] > thr3;
        const float thr  = isin ? thr3 : thr2;
        const float ld   = normcdff((rl[t] - thr) / sd[t]);
        out[2162688 + (size_t)n * 64 + e] = ld;
    }
}

// ============================================================================
// expert_mask fill: mask[e][j][n] = (selected[n][j] == e), float4 stores.
// ============================================================================
__global__ __launch_bounds__(256) void mask_kernel(float* __restrict__ out)
{
    const int idx = (blockIdx.x * 256 + threadIdx.x) * 4;   // over 2,097,152
    const int r  = idx >> 14;      // row 0..127 (= e*2 + j)
    const int n0 = idx & 16383;
    const int e  = r >> 1;
    const int j  = r & 1;
    float4 v;
    v.x = (g_sel[(n0 + 0) * 2 + j] == e) ? 1.f : 0.f;
    v.y = (g_sel[(n0 + 1) * 2 + j] == e) ? 1.f : 0.f;
    v.z = (g_sel[(n0 + 2) * 2 + j] == e) ? 1.f : 0.f;
    v.w = (g_sel[(n0 + 3) * 2 + j] == e) ? 1.f : 0.f;
    *(float4*)(out + 65536 + idx) = v;
}

extern "C" void kernel_launch(void* const* d_in, const int* in_sizes, int n_in,
                              void* d_out, int out_size)
{
    const float* x     = (const float*)d_in[0];
    const float* wg    = (const float*)d_in[1];
    const float* wn    = (const float*)d_in[2];
    const float* noise = (const float*)d_in[3];
    float* out = (float*)d_out;

    dim3 ggrid(N_TOK / 128, 2);            // 128 token-tiles x 2 K-splits
    gemm_kernel<<<ggrid, 256>>>(x, wg, wn);
    route_kernel<<<N_TOK / 8, 256>>>(noise, out);   // 8 warps/block = 8 tokens
    mask_kernel<<<2048, 256>>>(out);                // 2,097,152 / 1024
}

// round 3
// speedup vs baseline: 1.1597x; 1.1597x over previous
#include <cuda_runtime.h>
#include <math.h>
#include <math_constants.h>
#include <cstdint>

#define N_TOK 16384
#define DIMK  2048
#define NOUT  128          // 64 gate + 64 noise logit columns
#define BM    64
#define BK    32
#define NSTAGE_IT (DIMK / BK)   // 64 k-chunks
// smem layout (floats), padded row stride 36 (conflict-free for frag LDS + STS.128)
#define AROWS BM
#define BROWS 128
#define PAD_STRIDE 36
#define A_SZ   (AROWS * PAD_STRIDE)          // 2304 floats
#define B_SZ   (BROWS * PAD_STRIDE)          // 4608 floats
#define STAGE_F (2 * A_SZ + 2 * B_SZ)        // AH, AL, BH, BL = 13824 floats
#define SMEM_BYTES (2 * STAGE_F * 4)         // 110592 B

// ---- scratch (no allocations allowed) ----
__device__ float g_logits[N_TOK * NOUT];   // 8 MB
__device__ int   g_sel[N_TOK * 2];

__device__ __forceinline__ uint32_t f2tf32(float f) {
    uint32_t r;
    asm("cvt.rna.tf32.f32 %0, %1;" : "=r"(r) : "f"(f));
    return r;
}
__device__ __forceinline__ void split2(float v, uint32_t& h, uint32_t& l) {
    h = f2tf32(v);
    l = f2tf32(v - __uint_as_float(h));
}
__device__ __forceinline__ void mma_tf32(float* c, const uint32_t* a, const uint32_t* b) {
    asm volatile(
        "mma.sync.aligned.m16n8k8.row.col.f32.tf32.tf32.f32 "
        "{%0,%1,%2,%3}, {%4,%5,%6,%7}, {%8,%9}, {%0,%1,%2,%3};"
        : "+f"(c[0]), "+f"(c[1]), "+f"(c[2]), "+f"(c[3])
        : "r"(a[0]), "r"(a[1]), "r"(a[2]), "r"(a[3]), "r"(b[0]), "r"(b[1]));
}

// ============================================================================
// 3xTF32 mma.sync GEMM: logits[n][e] = sum_d x[n][d]*W[e][d]
// CTA: 64 tokens x 128 cols, 8 warps (2 m x 4 n), warp tile 32x32.
// ============================================================================
__global__ __launch_bounds__(256, 2) void gemm_kernel(
    const float* __restrict__ x,
    const float* __restrict__ wg,
    const float* __restrict__ wn)
{
    extern __shared__ float sm[];
    const int tid  = threadIdx.x;
    const int wid  = tid >> 5;
    const int lane = tid & 31;
    const int g    = lane >> 2;     // 0..7
    const int t    = lane & 3;      // 0..3
    const int warp_m = wid & 1;     // 0..1 -> 32-row half
    const int warp_n = wid >> 1;    // 0..3 -> 32-col quarter
    const int blockRow = blockIdx.x * BM;

    // global-load mapping
    const int ar  = tid >> 2;            // 0..63
    const int akq = (tid & 3) * 8;       // 0,8,16,24
    const int br  = tid >> 1;            // 0..127
    const int bkq = (tid & 1) * 16;      // 0,16
    const float* asrc = x + (size_t)(blockRow + ar) * DIMK + akq;
    const float* bsrc = ((br < 64) ? (wg + (size_t)br * DIMK)
                                   : (wn + (size_t)(br - 64) * DIMK)) + bkq;

    float acc[2][4][4];
    #pragma unroll
    for (int mf = 0; mf < 2; mf++)
        #pragma unroll
        for (int nf = 0; nf < 4; nf++)
            #pragma unroll
            for (int r = 0; r < 4; r++) acc[mf][nf][r] = 0.f;

    float4 aL[2], bL[4];

    // ---- prologue: load + convert + store stage 0 ----
    #pragma unroll
    for (int q = 0; q < 2; q++) aL[q] = *(const float4*)(asrc + q * 4);
    #pragma unroll
    for (int q = 0; q < 4; q++) bL[q] = *(const float4*)(bsrc + q * 4);
    {
        float* AH = sm;                 float* AL = sm + A_SZ;
        float* BH = sm + 2 * A_SZ;      float* BL = sm + 2 * A_SZ + B_SZ;
        #pragma unroll
        for (int q = 0; q < 2; q++) {
            uint4 h, l;
            split2(aL[q].x, h.x, l.x); split2(aL[q].y, h.y, l.y);
            split2(aL[q].z, h.z, l.z); split2(aL[q].w, h.w, l.w);
            *(uint4*)(AH + ar * PAD_STRIDE + akq + q * 4) = h;
            *(uint4*)(AL + ar * PAD_STRIDE + akq + q * 4) = l;
        }
        #pragma unroll
        for (int q = 0; q < 4; q++) {
            uint4 h, l;
            split2(bL[q].x, h.x, l.x); split2(bL[q].y, h.y, l.y);
            split2(bL[q].z, h.z, l.z); split2(bL[q].w, h.w, l.w);
            *(uint4*)(BH + br * PAD_STRIDE + bkq + q * 4) = h;
            *(uint4*)(BL + br * PAD_STRIDE + bkq + q * 4) = l;
        }
    }
    __syncthreads();

    const int arow0 = warp_m * 32;
    const int ncol0 = warp_n * 32;

    for (int i = 0; i < NSTAGE_IT; i++) {
        // prefetch next chunk
        if (i + 1 < NSTAGE_IT) {
            const int k0 = (i + 1) * BK;
            #pragma unroll
            for (int q = 0; q < 2; q++) aL[q] = *(const float4*)(asrc + k0 + q * 4);
            #pragma unroll
            for (int q = 0; q < 4; q++) bL[q] = *(const float4*)(bsrc + k0 + q * 4);
        }

        // ---- compute current stage ----
        const float* st = sm + (i & 1) * STAGE_F;
        const float* AH = st;                const float* ALo = st + A_SZ;
        const float* BH = st + 2 * A_SZ;     const float* BLo = st + 2 * A_SZ + B_SZ;
        #pragma unroll
        for (int ks = 0; ks < 4; ks++) {
            const int kk = ks * 8 + t;
            uint32_t Ah[2][4], Al[2][4], Bh[4][2], Bl[4][2];
            #pragma unroll
            for (int mf = 0; mf < 2; mf++) {
                const int base = (arow0 + mf * 16 + g) * PAD_STRIDE + kk;
                Ah[mf][0] = __float_as_uint(AH[base]);
                Ah[mf][1] = __float_as_uint(AH[base + 8 * PAD_STRIDE]);
                Ah[mf][2] = __float_as_uint(AH[base + 4]);
                Ah[mf][3] = __float_as_uint(AH[base + 8 * PAD_STRIDE + 4]);
                Al[mf][0] = __float_as_uint(ALo[base]);
                Al[mf][1] = __float_as_uint(ALo[base + 8 * PAD_STRIDE]);
                Al[mf][2] = __float_as_uint(ALo[base + 4]);
                Al[mf][3] = __float_as_uint(ALo[base + 8 * PAD_STRIDE + 4]);
            }
            #pragma unroll
            for (int nf = 0; nf < 4; nf++) {
                const int base = (ncol0 + nf * 8 + g) * PAD_STRIDE + kk;
                Bh[nf][0] = __float_as_uint(BH[base]);
                Bh[nf][1] = __float_as_uint(BH[base + 4]);
                Bl[nf][0] = __float_as_uint(BLo[base]);
                Bl[nf][1] = __float_as_uint(BLo[base + 4]);
            }
            #pragma unroll
            for (int nf = 0; nf < 4; nf++)
                #pragma unroll
                for (int mf = 0; mf < 2; mf++) {
                    mma_tf32(acc[mf][nf], Ah[mf], Bh[nf]);
                    mma_tf32(acc[mf][nf], Ah[mf], Bl[nf]);
                    mma_tf32(acc[mf][nf], Al[mf], Bh[nf]);
                }
        }

        // ---- convert + store next stage ----
        if (i + 1 < NSTAGE_IT) {
            float* nst = sm + ((i + 1) & 1) * STAGE_F;
            float* AHn = nst;               float* ALn = nst + A_SZ;
            float* BHn = nst + 2 * A_SZ;    float* BLn = nst + 2 * A_SZ + B_SZ;
            #pragma unroll
            for (int q = 0; q < 2; q++) {
                uint4 h, l;
                split2(aL[q].x, h.x, l.x); split2(aL[q].y, h.y, l.y);
                split2(aL[q].z, h.z, l.z); split2(aL[q].w, h.w, l.w);
                *(uint4*)(AHn + ar * PAD_STRIDE + akq + q * 4) = h;
                *(uint4*)(ALn + ar * PAD_STRIDE + akq + q * 4) = l;
            }
            #pragma unroll
            for (int q = 0; q < 4; q++) {
                uint4 h, l;
                split2(bL[q].x, h.x, l.x); split2(bL[q].y, h.y, l.y);
                split2(bL[q].z, h.z, l.z); split2(bL[q].w, h.w, l.w);
                *(uint4*)(BHn + br * PAD_STRIDE + bkq + q * 4) = h;
                *(uint4*)(BLn + br * PAD_STRIDE + bkq + q * 4) = l;
            }
        }
        __syncthreads();
    }

    // ---- epilogue: write C tile to g_logits ----
    #pragma unroll
    for (int mf = 0; mf < 2; mf++) {
        const int m = blockRow + arow0 + mf * 16 + g;
        #pragma unroll
        for (int nf = 0; nf < 4; nf++) {
            const int n = ncol0 + nf * 8 + 2 * t;
            *(float2*)(g_logits + (size_t)m * NOUT + n) =
                make_float2(acc[mf][nf][0], acc[mf][nf][1]);
            *(float2*)(g_logits + (size_t)(m + 8) * NOUT + n) =
                make_float2(acc[mf][nf][2], acc[mf][nf][3]);
        }
    }
}

// ============================================================================
// Routing epilogue: 1 warp per token (64 experts, 2 per lane).
// Output layout (float32): rw[n][2] | sel[n][2] | mask[e][j][n] | load[n][64]
// ============================================================================
__global__ __launch_bounds__(256) void route_kernel(
    const float* __restrict__ noise, float* __restrict__ out)
{
    const int n    = (blockIdx.x * blockDim.x + threadIdx.x) >> 5;
    const int lane = threadIdx.x & 31;
    if (n >= N_TOK) return;

    float rl[2], sv[2], sd[2];
    #pragma unroll
    for (int t = 0; t < 2; t++) {
        const int e = lane * 2 + t;
        const float r = g_logits[(size_t)n * NOUT + e];
        const float w = g_logits[(size_t)n * NOUT + 64 + e];
        const float sp  = fmaxf(w, 0.f) + log1pf(expf(-fabsf(w)));
        const float sdv = sp + 0.01f;
        rl[t] = r;
        sd[t] = sdv;
        sv[t] = fmaf(noise[(size_t)n * 64 + e], sdv, r);
    }

    float vtop[3]; int itop[3];
    float cur0 = sv[0], cur1 = sv[1];
    #pragma unroll
    for (int r = 0; r < 3; r++) {
        float bv; int bi;
        if (cur0 >= cur1) { bv = cur0; bi = lane * 2; }
        else              { bv = cur1; bi = lane * 2 + 1; }
        #pragma unroll
        for (int off = 16; off; off >>= 1) {
            const float ov = __shfl_xor_sync(0xffffffffu, bv, off);
            const int   oi = __shfl_xor_sync(0xffffffffu, bi, off);
            if (ov > bv || (ov == bv && oi < bi)) { bv = ov; bi = oi; }
        }
        vtop[r] = bv; itop[r] = bi;
        if ((bi >> 1) == lane) {
            if (bi & 1) cur1 = -CUDART_INF_F; else cur0 = -CUDART_INF_F;
        }
    }

    const float thr2 = vtop[1];
    const float thr3 = vtop[2];

    if (lane == 0) {
        const float a  = expf(vtop[1] - vtop[0]);
        const float s  = 1.f + a;
        out[n * 2 + 0] = 1.f / s;
        out[n * 2 + 1] = a / s;
        out[32768 + n * 2 + 0] = (float)itop[0];
        out[32768 + n * 2 + 1] = (float)itop[1];
        g_sel[n * 2 + 0] = itop[0];
        g_sel[n * 2 + 1] = itop[1];
    }

    #pragma unroll
    for (int t = 0; t < 2; t++) {
        const int e = lane * 2 + t;
        const bool  isin = sv[t] > thr3;
        const float thr  = isin ? thr3 : thr2;
        const float ld   = normcdff((rl[t] - thr) / sd[t]);
        out[2162688 + (size_t)n * 64 + e] = ld;
    }
}

// ============================================================================
// expert_mask fill: mask[e][j][n] = (selected[n][j] == e), float4 stores.
// ============================================================================
__global__ __launch_bounds__(256) void mask_kernel(float* __restrict__ out)
{
    const int idx = (blockIdx.x * 256 + threadIdx.x) * 4;
    const int r  = idx >> 14;
    const int n0 = idx & 16383;
    const int e  = r >> 1;
    const int j  = r & 1;
    float4 v;
    v.x = (g_sel[(n0 + 0) * 2 + j] == e) ? 1.f : 0.f;
    v.y = (g_sel[(n0 + 1) * 2 + j] == e) ? 1.f : 0.f;
    v.z = (g_sel[(n0 + 2) * 2 + j] == e) ? 1.f : 0.f;
    v.w = (g_sel[(n0 + 3) * 2 + j] == e) ? 1.f : 0.f;
    *(float4*)(out + 65536 + idx) = v;
}

extern "C" void kernel_launch(void* const* d_in, const int* in_sizes, int n_in,
                              void* d_out, int out_size)
{
    const float* x     = (const float*)d_in[0];
    const float* wg    = (const float*)d_in[1];
    const float* wn    = (const float*)d_in[2];
    const float* noise = (const float*)d_in[3];
    float* out = (float*)d_out;

    cudaFuncSetAttribute(gemm_kernel,
                         cudaFuncAttributeMaxDynamicSharedMemorySize, SMEM_BYTES);

    gemm_kernel<<<N_TOK / BM, 256, SMEM_BYTES>>>(x, wg, wn);
    route_kernel<<<N_TOK / 8, 256>>>(noise, out);
    mask_kernel<<<2048, 256>>>(out);
}

// round 4
// speedup vs baseline: 1.1727x; 1.0112x over previous
#include <cuda_runtime.h>
#include <math.h>
#include <math_constants.h>
#include <cstdint>

#define N_TOK 16384
#define DIMK  2048
#define NOUT  128          // 64 gate + 64 noise logit columns
#define BM    64
#define BK    32
#define NCHUNK (DIMK / BK)      // 64
// A smem: padded row stride 36 floats (conflict-free frag LDS, clean STS.128)
#define PAD_STRIDE 36
#define A_SZ   (BM * PAD_STRIDE)             // 2304 floats
#define STAGE_F (2 * A_SZ)                   // AH + AL
#define SMEM_BYTES (2 * STAGE_F * 4)         // 36864 B

// ---- scratch (no allocations allowed) ----
// B fragments: [chunk i][n 0..127][ks 0..3][t 0..3] -> float4(b0h,b1h,b0l,b1l)
//   b0 = W[n][i*32+ks*8+t], b1 = W[n][i*32+ks*8+t+4]; +2048 pad for prefetch OOB
__device__ float4 g_bfrag[NCHUNK * 2048 + 2048];   // 2 MB + pad
__device__ float  g_logits[N_TOK * NOUT];          // 8 MB
__device__ int    g_sel[N_TOK * 2];

__device__ __forceinline__ uint32_t f2tf32(float f) {
    uint32_t r;
    asm("cvt.rna.tf32.f32 %0, %1;" : "=r"(r) : "f"(f));
    return r;
}
__device__ __forceinline__ void split2(float v, uint32_t& h, uint32_t& l) {
    h = f2tf32(v);
    l = f2tf32(v - __uint_as_float(h));
}
__device__ __forceinline__ void mma_tf32(float* c, const uint32_t* a,
                                         uint32_t b0, uint32_t b1) {
    asm volatile(
        "mma.sync.aligned.m16n8k8.row.col.f32.tf32.tf32.f32 "
        "{%0,%1,%2,%3}, {%4,%5,%6,%7}, {%8,%9}, {%0,%1,%2,%3};"
        : "+f"(c[0]), "+f"(c[1]), "+f"(c[2]), "+f"(c[3])
        : "r"(a[0]), "r"(a[1]), "r"(a[2]), "r"(a[3]), "r"(b0), "r"(b1));
}

// ============================================================================
// Pre-split B (w_gate;w_noise) into fragment-ordered tf32 hi/lo scratch.
// 131072 threads, one float4 each, fully coalesced stores.
// ============================================================================
__global__ __launch_bounds__(256) void presplit_kernel(
    const float* __restrict__ wg, const float* __restrict__ wn)
{
    const int idx = blockIdx.x * 256 + threadIdx.x;   // over 131072
    const int t  = idx & 3;
    const int ks = (idx >> 2) & 3;
    const int n  = (idx >> 4) & 127;
    const int i  = idx >> 11;
    const float* src = (n < 64) ? (wg + (size_t)n * DIMK)
                                : (wn + (size_t)(n - 64) * DIMK);
    const int k = i * 32 + ks * 8 + t;
    const float b0 = src[k];
    const float b1 = src[k + 4];
    uint32_t h0, l0, h1, l1;
    split2(b0, h0, l0);
    split2(b1, h1, l1);
    g_bfrag[idx] = make_float4(__uint_as_float(h0), __uint_as_float(h1),
                               __uint_as_float(l0), __uint_as_float(l1));
}

// ============================================================================
// 3xTF32 mma.sync GEMM: logits[n][e] = sum_d x[n][d]*W[e][d]
// CTA: 64 tokens x 128 cols, 8 warps (2m x 4n), warp tile 32x32.
// A: split in-kernel -> smem (double buffered). B: fragment LDG from scratch.
// ============================================================================
__global__ __launch_bounds__(256, 2) void gemm_kernel(const float* __restrict__ x)
{
    extern __shared__ float sm[];
    const int tid  = threadIdx.x;
    const int wid  = tid >> 5;
    const int lane = tid & 31;
    const int g    = lane >> 2;     // 0..7
    const int t    = lane & 3;      // 0..3
    const int warp_m = wid & 1;
    const int warp_n = wid >> 1;
    const int blockRow = blockIdx.x * BM;
    const int arow0 = warp_m * 32;
    const int ncol0 = warp_n * 32;

    // A global-load mapping: thread -> (row ar, k-slice akq..akq+7)
    const int ar  = tid >> 2;            // 0..63
    const int akq = (tid & 3) * 8;       // 0,8,16,24
    const float* asrc = x + (size_t)(blockRow + ar) * DIMK + akq;

    // B fragment base (float4 index): + i*2048 + nf*128 + ks*4
    const float4* bbase = g_bfrag + ((ncol0 + g) * 16 + t);

    float acc[2][4][4];
    #pragma unroll
    for (int mf = 0; mf < 2; mf++)
        #pragma unroll
        for (int nf = 0; nf < 4; nf++)
            #pragma unroll
            for (int r = 0; r < 4; r++) acc[mf][nf][r] = 0.f;

    float4 aL[2];

    // ---- prologue: A chunk 0 -> smem stage 0 ----
    aL[0] = *(const float4*)(asrc);
    aL[1] = *(const float4*)(asrc + 4);
    {
        float* AH = sm;
        float* AL = sm + A_SZ;
        #pragma unroll
        for (int q = 0; q < 2; q++) {
            uint4 h, l;
            split2(aL[q].x, h.x, l.x); split2(aL[q].y, h.y, l.y);
            split2(aL[q].z, h.z, l.z); split2(aL[q].w, h.w, l.w);
            *(uint4*)(AH + ar * PAD_STRIDE + akq + q * 4) = h;
            *(uint4*)(AL + ar * PAD_STRIDE + akq + q * 4) = l;
        }
    }
    __syncthreads();

    // B register double-buffer: preload (i=0, ks=0)
    float4 Bbuf[2][4];
    #pragma unroll
    for (int nf = 0; nf < 4; nf++) Bbuf[0][nf] = bbase[nf * 128];

    for (int i = 0; i < NCHUNK; i++) {
        // A global prefetch for chunk i+1
        if (i + 1 < NCHUNK) {
            aL[0] = *(const float4*)(asrc + (i + 1) * BK);
            aL[1] = *(const float4*)(asrc + (i + 1) * BK + 4);
        }

        const float* AH  = sm + (i & 1) * STAGE_F;
        const float* ALo = AH + A_SZ;
        const float4* bi = bbase + i * 2048;

        #pragma unroll
        for (int ks = 0; ks < 4; ks++) {
            const int cur = ks & 1, nxt = cur ^ 1;
            // prefetch next B fragments (next ks, or next chunk's ks=0)
            const float4* bn = (ks < 3) ? (bi + (ks + 1) * 4) : (bi + 2048);
            #pragma unroll
            for (int nf = 0; nf < 4; nf++) Bbuf[nxt][nf] = bn[nf * 128];

            // A fragments (scalar LDS, conflict-free via stride 36)
            const int kk = ks * 8 + t;
            uint32_t Ah[2][4], Al[2][4];
            #pragma unroll
            for (int mf = 0; mf < 2; mf++) {
                const int base = (arow0 + mf * 16 + g) * PAD_STRIDE + kk;
                Ah[mf][0] = __float_as_uint(AH[base]);
                Ah[mf][1] = __float_as_uint(AH[base + 8 * PAD_STRIDE]);
                Ah[mf][2] = __float_as_uint(AH[base + 4]);
                Ah[mf][3] = __float_as_uint(AH[base + 8 * PAD_STRIDE + 4]);
                Al[mf][0] = __float_as_uint(ALo[base]);
                Al[mf][1] = __float_as_uint(ALo[base + 8 * PAD_STRIDE]);
                Al[mf][2] = __float_as_uint(ALo[base + 4]);
                Al[mf][3] = __float_as_uint(ALo[base + 8 * PAD_STRIDE + 4]);
            }

            #pragma unroll
            for (int nf = 0; nf < 4; nf++) {
                const uint32_t bh0 = __float_as_uint(Bbuf[cur][nf].x);
                const uint32_t bh1 = __float_as_uint(Bbuf[cur][nf].y);
                const uint32_t bl0 = __float_as_uint(Bbuf[cur][nf].z);
                const uint32_t bl1 = __float_as_uint(Bbuf[cur][nf].w);
                #pragma unroll
                for (int mf = 0; mf < 2; mf++) {
                    mma_tf32(acc[mf][nf], Ah[mf], bh0, bh1);
                    mma_tf32(acc[mf][nf], Ah[mf], bl0, bl1);
                    mma_tf32(acc[mf][nf], Al[mf], bh0, bh1);
                }
            }
        }

        // convert + store A for chunk i+1
        if (i + 1 < NCHUNK) {
            float* AHn = sm + ((i + 1) & 1) * STAGE_F;
            float* ALn = AHn + A_SZ;
            #pragma unroll
            for (int q = 0; q < 2; q++) {
                uint4 h, l;
                split2(aL[q].x, h.x, l.x); split2(aL[q].y, h.y, l.y);
                split2(aL[q].z, h.z, l.z); split2(aL[q].w, h.w, l.w);
                *(uint4*)(AHn + ar * PAD_STRIDE + akq + q * 4) = h;
                *(uint4*)(ALn + ar * PAD_STRIDE + akq + q * 4) = l;
            }
        }
        __syncthreads();
    }

    // ---- epilogue: write C tile to g_logits ----
    #pragma unroll
    for (int mf = 0; mf < 2; mf++) {
        const int m = blockRow + arow0 + mf * 16 + g;
        #pragma unroll
        for (int nf = 0; nf < 4; nf++) {
            const int n = ncol0 + nf * 8 + 2 * t;
            *(float2*)(g_logits + (size_t)m * NOUT + n) =
                make_float2(acc[mf][nf][0], acc[mf][nf][1]);
            *(float2*)(g_logits + (size_t)(m + 8) * NOUT + n) =
                make_float2(acc[mf][nf][2], acc[mf][nf][3]);
        }
    }
}

// ============================================================================
// Routing epilogue: 1 warp per token (64 experts, 2 per lane).
// Output layout (float32): rw[n][2] | sel[n][2] | mask[e][j][n] | load[n][64]
// ============================================================================
__global__ __launch_bounds__(256) void route_kernel(
    const float* __restrict__ noise, float* __restrict__ out)
{
    const int n    = (blockIdx.x * blockDim.x + threadIdx.x) >> 5;
    const int lane = threadIdx.x & 31;
    if (n >= N_TOK) return;

    float rl[2], sv[2], sd[2];
    #pragma unroll
    for (int t = 0; t < 2; t++) {
        const int e = lane * 2 + t;
        const float r = g_logits[(size_t)n * NOUT + e];
        const float w = g_logits[(size_t)n * NOUT + 64 + e];
        const float sp  = fmaxf(w, 0.f) + log1pf(expf(-fabsf(w)));
        const float sdv = sp + 0.01f;
        rl[t] = r;
        sd[t] = sdv;
        sv[t] = fmaf(noise[(size_t)n * 64 + e], sdv, r);
    }

    float vtop[3]; int itop[3];
    float cur0 = sv[0], cur1 = sv[1];
    #pragma unroll
    for (int r = 0; r < 3; r++) {
        float bv; int bi;
        if (cur0 >= cur1) { bv = cur0; bi = lane * 2; }
        else              { bv = cur1; bi = lane * 2 + 1; }
        #pragma unroll
        for (int off = 16; off; off >>= 1) {
            const float ov = __shfl_xor_sync(0xffffffffu, bv, off);
            const int   oi = __shfl_xor_sync(0xffffffffu, bi, off);
            if (ov > bv || (ov == bv && oi < bi)) { bv = ov; bi = oi; }
        }
        vtop[r] = bv; itop[r] = bi;
        if ((bi >> 1) == lane) {
            if (bi & 1) cur1 = -CUDART_INF_F; else cur0 = -CUDART_INF_F;
        }
    }

    const float thr2 = vtop[1];
    const float thr3 = vtop[2];

    if (lane == 0) {
        const float a  = expf(vtop[1] - vtop[0]);
        const float s  = 1.f + a;
        out[n * 2 + 0] = 1.f / s;
        out[n * 2 + 1] = a / s;
        out[32768 + n * 2 + 0] = (float)itop[0];
        out[32768 + n * 2 + 1] = (float)itop[1];
        g_sel[n * 2 + 0] = itop[0];
        g_sel[n * 2 + 1] = itop[1];
    }

    #pragma unroll
    for (int t = 0; t < 2; t++) {
        const int e = lane * 2 + t;
        const bool  isin = sv[t] > thr3;
        const float thr  = isin ? thr3 : thr2;
        const float ld   = normcdff((rl[t] - thr) / sd[t]);
        out[2162688 + (size_t)n * 64 + e] = ld;
    }
}

// ============================================================================
// expert_mask fill: mask[e][j][n] = (selected[n][j] == e), float4 stores.
// ============================================================================
__global__ __launch_bounds__(256) void mask_kernel(float* __restrict__ out)
{
    const int idx = (blockIdx.x * 256 + threadIdx.x) * 4;
    const int r  = idx >> 14;
    const int n0 = idx & 16383;
    const int e  = r >> 1;
    const int j  = r & 1;
    float4 v;
    v.x = (g_sel[(n0 + 0) * 2 + j] == e) ? 1.f : 0.f;
    v.y = (g_sel[(n0 + 1) * 2 + j] == e) ? 1.f : 0.f;
    v.z = (g_sel[(n0 + 2) * 2 + j] == e) ? 1.f : 0.f;
    v.w = (g_sel[(n0 + 3) * 2 + j] == e) ? 1.f : 0.f;
    *(float4*)(out + 65536 + idx) = v;
}

extern "C" void kernel_launch(void* const* d_in, const int* in_sizes, int n_in,
                              void* d_out, int out_size)
{
    const float* x     = (const float*)d_in[0];
    const float* wg    = (const float*)d_in[1];
    const float* wn    = (const float*)d_in[2];
    const float* noise = (const float*)d_in[3];
    float* out = (float*)d_out;

    cudaFuncSetAttribute(gemm_kernel,
                         cudaFuncAttributeMaxDynamicSharedMemorySize, SMEM_BYTES);

    presplit_kernel<<<512, 256>>>(wg, wn);
    gemm_kernel<<<N_TOK / BM, 256, SMEM_BYTES>>>(x);
    route_kernel<<<N_TOK / 8, 256>>>(noise, out);
    mask_kernel<<<2048, 256>>>(out);
}

// round 5
// speedup vs baseline: 2.2757x; 1.9406x over previous
#include <cuda_runtime.h>
#include <cuda_fp16.h>
#include <math.h>
#include <math_constants.h>
#include <cstdint>

#define N_TOK 16384
#define DIMK  2048
#define NOUT  128          // 64 gate + 64 noise logit columns
#define BM    64
#define BK    64           // fp32 k elems per smem stage (4 x k16 blocks)
#define NCHUNK (DIMK / BK)      // 32
// A smem: packed f16x2 (hi,lo), u32 row stride 36 (conflict-free LDS + STS.128)
#define PAD_U 36
#define A_SZU (BM * PAD_U)                  // 2304 u32
#define STAGE_U (2 * A_SZU)                 // AH + AL
#define SMEM_BYTES (2 * STAGE_U * 4)        // 36864 B

#define BSCALE     512.0f                   // 2^9 weight pre-scale
#define INV_BSCALE (1.0f / 512.0f)

// ---- scratch (no allocations allowed) ----
// B fragments: [ib 0..127][n 0..127][t 0..3] -> uint4(hi_pair0, hi_pair1, lo_pair0, lo_pair1)
//   pair0 = W[n][ib*16+2t .. +1], pair1 = W[n][ib*16+2t+8 .. +1]  (scaled by BSCALE)
__device__ uint4 g_bfrag[128 * 128 * 4 + 2048];   // 1 MB + prefetch pad
__device__ float g_logits[N_TOK * NOUT];          // 8 MB
__device__ int   g_sel[N_TOK * 2];

__device__ __forceinline__ uint32_t pack_h2(float lo, float hi) {
    __half2 h = __halves2half2(__float2half_rn(lo), __float2half_rn(hi));
    return *reinterpret_cast<uint32_t*>(&h);
}
__device__ __forceinline__ void mma_f16(float* c, const uint32_t* a,
                                        uint32_t b0, uint32_t b1) {
    asm volatile(
        "mma.sync.aligned.m16n8k16.row.col.f32.f16.f16.f32 "
        "{%0,%1,%2,%3}, {%4,%5,%6,%7}, {%8,%9}, {%0,%1,%2,%3};"
        : "+f"(c[0]), "+f"(c[1]), "+f"(c[2]), "+f"(c[3])
        : "r"(a[0]), "r"(a[1]), "r"(a[2]), "r"(a[3]), "r"(b0), "r"(b1));
}

// ============================================================================
// Pre-split B (w_gate;w_noise), scaled by BSCALE, into fp16 hi/lo fragments.
// 65536 threads, one uint4 each, coalesced.
// ============================================================================
__global__ __launch_bounds__(256) void presplit_kernel(
    const float* __restrict__ wg, const float* __restrict__ wn)
{
    const int idx = blockIdx.x * 256 + threadIdx.x;   // 0..65535
    const int t  = idx & 3;
    const int n  = (idx >> 2) & 127;
    const int ib = idx >> 9;                           // k16 block 0..127
    const float* src = (n < 64) ? (wg + (size_t)n * DIMK)
                                : (wn + (size_t)(n - 64) * DIMK);
    const int k0 = ib * 16 + 2 * t;
    const float v0 = src[k0]     * BSCALE;
    const float v1 = src[k0 + 1] * BSCALE;
    const float v2 = src[k0 + 8] * BSCALE;
    const float v3 = src[k0 + 9] * BSCALE;
    const __half h0 = __float2half_rn(v0), h1 = __float2half_rn(v1);
    const __half h2 = __float2half_rn(v2), h3 = __float2half_rn(v3);
    const float l0 = v0 - __half2float(h0), l1 = v1 - __half2float(h1);
    const float l2 = v2 - __half2float(h2), l3 = v3 - __half2float(h3);
    uint4 o;
    {
        __half2 p;
        p = __halves2half2(h0, h1); o.x = *reinterpret_cast<uint32_t*>(&p);
        p = __halves2half2(h2, h3); o.y = *reinterpret_cast<uint32_t*>(&p);
    }
    o.z = pack_h2(l0, l1);
    o.w = pack_h2(l2, l3);
    g_bfrag[idx] = o;
}

// ============================================================================
// fp16x3 mma.sync GEMM: logits[n][e] = sum_d x[n][d]*W[e][d]
// CTA: 64 tokens x 128 cols, 8 warps (2m x 4n), warp tile 32x32, m16n8k16.
// A: split in-kernel -> packed-f16x2 smem (double buffered). B: fragment LDG.
// ============================================================================
__global__ __launch_bounds__(256, 2) void gemm_kernel(const float* __restrict__ x)
{
    extern __shared__ uint32_t sm[];
    const int tid  = threadIdx.x;
    const int wid  = tid >> 5;
    const int lane = tid & 31;
    const int g    = lane >> 2;     // 0..7
    const int t    = lane & 3;      // 0..3
    const int warp_m = wid & 1;
    const int warp_n = wid >> 1;
    const int blockRow = blockIdx.x * BM;
    const int arow0 = warp_m * 32;
    const int ncol0 = warp_n * 32;

    // A global-load mapping: row ar, 16-float k-slice
    const int ar  = tid >> 2;            // 0..63
    const int akq = (tid & 3) * 16;      // 0,16,32,48
    const float* asrc = x + (size_t)(blockRow + ar) * DIMK + akq;
    const int acol = (tid & 3) * 8;      // u32 col in smem

    // B fragment base (uint4 index): + ib*512 + nf*32
    const uint4* bbase = g_bfrag + ((ncol0 + g) * 4 + t);

    float acc[2][4][4];
    #pragma unroll
    for (int mf = 0; mf < 2; mf++)
        #pragma unroll
        for (int nf = 0; nf < 4; nf++)
            #pragma unroll
            for (int r = 0; r < 4; r++) acc[mf][nf][r] = 0.f;

    float4 aL[4];

    // ---- prologue: A chunk 0 -> smem stage 0 ----
    #pragma unroll
    for (int q = 0; q < 4; q++) aL[q] = *(const float4*)(asrc + q * 4);
    {
        uint32_t* AH = sm;
        uint32_t* AL = sm + A_SZU;
        #pragma unroll
        for (int q = 0; q < 2; q++) {
            const float f0 = aL[2*q].x,   f1 = aL[2*q].y,
                        f2 = aL[2*q].z,   f3 = aL[2*q].w,
                        f4 = aL[2*q+1].x, f5 = aL[2*q+1].y,
                        f6 = aL[2*q+1].z, f7 = aL[2*q+1].w;
            const __half h0=__float2half_rn(f0), h1=__float2half_rn(f1),
                         h2=__float2half_rn(f2), h3=__float2half_rn(f3),
                         h4=__float2half_rn(f4), h5=__float2half_rn(f5),
                         h6=__float2half_rn(f6), h7=__float2half_rn(f7);
            uint4 hv, lv;
            { __half2 p=__halves2half2(h0,h1); hv.x=*reinterpret_cast<uint32_t*>(&p);
              p=__halves2half2(h2,h3); hv.y=*reinterpret_cast<uint32_t*>(&p);
              p=__halves2half2(h4,h5); hv.z=*reinterpret_cast<uint32_t*>(&p);
              p=__halves2half2(h6,h7); hv.w=*reinterpret_cast<uint32_t*>(&p); }
            lv.x = pack_h2(f0-__half2float(h0), f1-__half2float(h1));
            lv.y = pack_h2(f2-__half2float(h2), f3-__half2float(h3));
            lv.z = pack_h2(f4-__half2float(h4), f5-__half2float(h5));
            lv.w = pack_h2(f6-__half2float(h6), f7-__half2float(h7));
            *(uint4*)(AH + ar * PAD_U + acol + q * 4) = hv;
            *(uint4*)(AL + ar * PAD_U + acol + q * 4) = lv;
        }
    }
    __syncthreads();

    // B register double-buffer: preload (i=0, ks=0)
    uint4 Bbuf[2][4];
    #pragma unroll
    for (int nf = 0; nf < 4; nf++) Bbuf[0][nf] = bbase[nf * 32];

    for (int i = 0; i < NCHUNK; i++) {
        // A global prefetch for chunk i+1
        if (i + 1 < NCHUNK) {
            #pragma unroll
            for (int q = 0; q < 4; q++)
                aL[q] = *(const float4*)(asrc + (i + 1) * BK + q * 4);
        }

        const uint32_t* AH  = sm + (i & 1) * STAGE_U;
        const uint32_t* ALo = AH + A_SZU;
        const uint4* bi = bbase + (size_t)i * 2048;   // 4 ib per chunk

        #pragma unroll
        for (int ks = 0; ks < 4; ks++) {
            const int cur = ks & 1, nxt = cur ^ 1;
            const uint4* bn = (ks < 3) ? (bi + (ks + 1) * 512) : (bi + 2048);
            #pragma unroll
            for (int nf = 0; nf < 4; nf++) Bbuf[nxt][nf] = bn[nf * 32];

            // A fragments (scalar LDS u32, conflict-free via stride 36)
            const int kk = ks * 8 + t;
            uint32_t Ah[2][4], Al[2][4];
            #pragma unroll
            for (int mf = 0; mf < 2; mf++) {
                const int base = (arow0 + mf * 16 + g) * PAD_U + kk;
                Ah[mf][0] = AH[base];
                Ah[mf][1] = AH[base + 8 * PAD_U];
                Ah[mf][2] = AH[base + 4];
                Ah[mf][3] = AH[base + 8 * PAD_U + 4];
                Al[mf][0] = ALo[base];
                Al[mf][1] = ALo[base + 8 * PAD_U];
                Al[mf][2] = ALo[base + 4];
                Al[mf][3] = ALo[base + 8 * PAD_U + 4];
            }

            #pragma unroll
            for (int nf = 0; nf < 4; nf++) {
                const uint32_t bh0 = Bbuf[cur][nf].x, bh1 = Bbuf[cur][nf].y;
                const uint32_t bl0 = Bbuf[cur][nf].z, bl1 = Bbuf[cur][nf].w;
                #pragma unroll
                for (int mf = 0; mf < 2; mf++) {
                    mma_f16(acc[mf][nf], Ah[mf], bh0, bh1);
                    mma_f16(acc[mf][nf], Ah[mf], bl0, bl1);
                    mma_f16(acc[mf][nf], Al[mf], bh0, bh1);
                }
            }
        }

        // convert + store A for chunk i+1
        if (i + 1 < NCHUNK) {
            uint32_t* AHn = sm + ((i + 1) & 1) * STAGE_U;
            uint32_t* ALn = AHn + A_SZU;
            #pragma unroll
            for (int q = 0; q < 2; q++) {
                const float f0 = aL[2*q].x,   f1 = aL[2*q].y,
                            f2 = aL[2*q].z,   f3 = aL[2*q].w,
                            f4 = aL[2*q+1].x, f5 = aL[2*q+1].y,
                            f6 = aL[2*q+1].z, f7 = aL[2*q+1].w;
                const __half h0=__float2half_rn(f0), h1=__float2half_rn(f1),
                             h2=__float2half_rn(f2), h3=__float2half_rn(f3),
                             h4=__float2half_rn(f4), h5=__float2half_rn(f5),
                             h6=__float2half_rn(f6), h7=__float2half_rn(f7);
                uint4 hv, lv;
                { __half2 p=__halves2half2(h0,h1); hv.x=*reinterpret_cast<uint32_t*>(&p);
                  p=__halves2half2(h2,h3); hv.y=*reinterpret_cast<uint32_t*>(&p);
                  p=__halves2half2(h4,h5); hv.z=*reinterpret_cast<uint32_t*>(&p);
                  p=__halves2half2(h6,h7); hv.w=*reinterpret_cast<uint32_t*>(&p); }
                lv.x = pack_h2(f0-__half2float(h0), f1-__half2float(h1));
                lv.y = pack_h2(f2-__half2float(h2), f3-__half2float(h3));
                lv.z = pack_h2(f4-__half2float(h4), f5-__half2float(h5));
                lv.w = pack_h2(f6-__half2float(h6), f7-__half2float(h7));
                *(uint4*)(AHn + ar * PAD_U + acol + q * 4) = hv;
                *(uint4*)(ALn + ar * PAD_U + acol + q * 4) = lv;
            }
        }
        __syncthreads();
    }

    // ---- epilogue: unscale + write C tile to g_logits ----
    #pragma unroll
    for (int mf = 0; mf < 2; mf++) {
        const int m = blockRow + arow0 + mf * 16 + g;
        #pragma unroll
        for (int nf = 0; nf < 4; nf++) {
            const int n = ncol0 + nf * 8 + 2 * t;
            *(float2*)(g_logits + (size_t)m * NOUT + n) =
                make_float2(acc[mf][nf][0] * INV_BSCALE, acc[mf][nf][1] * INV_BSCALE);
            *(float2*)(g_logits + (size_t)(m + 8) * NOUT + n) =
                make_float2(acc[mf][nf][2] * INV_BSCALE, acc[mf][nf][3] * INV_BSCALE);
        }
    }
}

// ============================================================================
// Routing epilogue: 1 warp per token (64 experts, 2 per lane).
// Output layout (float32): rw[n][2] | sel[n][2] | mask[e][j][n] | load[n][64]
// ============================================================================
__global__ __launch_bounds__(256) void route_kernel(
    const float* __restrict__ noise, float* __restrict__ out)
{
    const int n    = (blockIdx.x * blockDim.x + threadIdx.x) >> 5;
    const int lane = threadIdx.x & 31;
    if (n >= N_TOK) return;

    float rl[2], sv[2], sd[2];
    #pragma unroll
    for (int t = 0; t < 2; t++) {
        const int e = lane * 2 + t;
        const float r = g_logits[(size_t)n * NOUT + e];
        const float w = g_logits[(size_t)n * NOUT + 64 + e];
        const float sp  = fmaxf(w, 0.f) + log1pf(expf(-fabsf(w)));
        const float sdv = sp + 0.01f;
        rl[t] = r;
        sd[t] = sdv;
        sv[t] = fmaf(noise[(size_t)n * 64 + e], sdv, r);
    }

    float vtop[3]; int itop[3];
    float cur0 = sv[0], cur1 = sv[1];
    #pragma unroll
    for (int r = 0; r < 3; r++) {
        float bv; int bi;
        if (cur0 >= cur1) { bv = cur0; bi = lane * 2; }
        else              { bv = cur1; bi = lane * 2 + 1; }
        #pragma unroll
        for (int off = 16; off; off >>= 1) {
            const float ov = __shfl_xor_sync(0xffffffffu, bv, off);
            const int   oi = __shfl_xor_sync(0xffffffffu, bi, off);
            if (ov > bv || (ov == bv && oi < bi)) { bv = ov; bi = oi; }
        }
        vtop[r] = bv; itop[r] = bi;
        if ((bi >> 1) == lane) {
            if (bi & 1) cur1 = -CUDART_INF_F; else cur0 = -CUDART_INF_F;
        }
    }

    const float thr2 = vtop[1];
    const float thr3 = vtop[2];

    if (lane == 0) {
        const float a  = expf(vtop[1] - vtop[0]);
        const float s  = 1.f + a;
        out[n * 2 + 0] = 1.f / s;
        out[n * 2 + 1] = a / s;
        out[32768 + n * 2 + 0] = (float)itop[0];
        out[32768 + n * 2 + 1] = (float)itop[1];
        g_sel[n * 2 + 0] = itop[0];
        g_sel[n * 2 + 1] = itop[1];
    }

    #pragma unroll
    for (int t = 0; t < 2; t++) {
        const int e = lane * 2 + t;
        const bool  isin = sv[t] > thr3;
        const float thr  = isin ? thr3 : thr2;
        const float ld   = normcdff((rl[t] - thr) / sd[t]);
        out[2162688 + (size_t)n * 64 + e] = ld;
    }
}

// ============================================================================
// expert_mask fill: mask[e][j][n] = (selected[n][j] == e), float4 stores.
// ============================================================================
__global__ __launch_bounds__(256) void mask_kernel(float* __restrict__ out)
{
    const int idx = (blockIdx.x * 256 + threadIdx.x) * 4;
    const int r  = idx >> 14;
    const int n0 = idx & 16383;
    const int e  = r >> 1;
    const int j  = r & 1;
    float4 v;
    v.x = (g_sel[(n0 + 0) * 2 + j] == e) ? 1.f : 0.f;
    v.y = (g_sel[(n0 + 1) * 2 + j] == e) ? 1.f : 0.f;
    v.z = (g_sel[(n0 + 2) * 2 + j] == e) ? 1.f : 0.f;
    v.w = (g_sel[(n0 + 3) * 2 + j] == e) ? 1.f : 0.f;
    *(float4*)(out + 65536 + idx) = v;
}

extern "C" void kernel_launch(void* const* d_in, const int* in_sizes, int n_in,
                              void* d_out, int out_size)
{
    const float* x     = (const float*)d_in[0];
    const float* wg    = (const float*)d_in[1];
    const float* wn    = (const float*)d_in[2];
    const float* noise = (const float*)d_in[3];
    float* out = (float*)d_out;

    cudaFuncSetAttribute(gemm_kernel,
                         cudaFuncAttributeMaxDynamicSharedMemorySize, SMEM_BYTES);

    presplit_kernel<<<256, 256>>>(wg, wn);
    gemm_kernel<<<N_TOK / BM, 256, SMEM_BYTES>>>(x);
    route_kernel<<<N_TOK / 8, 256>>>(noise, out);
    mask_kernel<<<2048, 256>>>(out);
}

// round 6
// speedup vs baseline: 2.3227x; 1.0206x over previous
#include <cuda_runtime.h>
#include <cuda_fp16.h>
#include <math.h>
#include <math_constants.h>
#include <cstdint>

#define N_TOK 16384
#define DIMK  2048
#define NOUT  128
#define BM    64
#define BK    64           // fp32 k elems per smem stage (4 x k16 blocks)
#define NCHUNK (DIMK / BK)      // 32
// A smem: packed f16x2 (hi,lo), u32 row stride 36 (conflict-free LDS + STS.128)
#define PAD_U 36
#define A_SZU (BM * PAD_U)                  // 2304 u32
#define STAGE_U (2 * A_SZU)                 // AH + AL
#define SMEM_BYTES (2 * STAGE_U * 4)        // 36864 B  (also covers epilogue use)

#define BSCALE     512.0f                   // 2^9 weight pre-scale
#define INV_BSCALE (1.0f / 512.0f)

// epilogue smem layout (reusing mainloop buffers)
#define L_STRIDE 132                        // floats per logit row
#define SEL_OFF  (64 * L_STRIDE)            // u32 offset of sel[128]

// output offsets (floats)
#define OUT_RW   0
#define OUT_SEL  32768
#define OUT_MASK 65536
#define OUT_LOAD 2162688

// ---- scratch (no allocations allowed) ----
// B fragments: [ib 0..127][n 0..127][t 0..3] -> uint4(hi0,hi1,lo0,lo1)
__device__ uint4 g_bfrag[128 * 128 * 4 + 2048];   // 1 MB + prefetch pad

__device__ __forceinline__ uint32_t pack_h2(float lo, float hi) {
    __half2 h = __halves2half2(__float2half_rn(lo), __float2half_rn(hi));
    return *reinterpret_cast<uint32_t*>(&h);
}
__device__ __forceinline__ void mma_f16(float* c, const uint32_t* a,
                                        uint32_t b0, uint32_t b1) {
    asm volatile(
        "mma.sync.aligned.m16n8k16.row.col.f32.f16.f16.f32 "
        "{%0,%1,%2,%3}, {%4,%5,%6,%7}, {%8,%9}, {%0,%1,%2,%3};"
        : "+f"(c[0]), "+f"(c[1]), "+f"(c[2]), "+f"(c[3])
        : "r"(a[0]), "r"(a[1]), "r"(a[2]), "r"(a[3]), "r"(b0), "r"(b1));
}

// ============================================================================
// Pre-split B (w_gate;w_noise), scaled by BSCALE, into fp16 hi/lo fragments.
// ============================================================================
__global__ __launch_bounds__(256) void presplit_kernel(
    const float* __restrict__ wg, const float* __restrict__ wn)
{
    const int idx = blockIdx.x * 256 + threadIdx.x;   // 0..65535
    const int t  = idx & 3;
    const int n  = (idx >> 2) & 127;
    const int ib = idx >> 9;
    const float* src = (n < 64) ? (wg + (size_t)n * DIMK)
                                : (wn + (size_t)(n - 64) * DIMK);
    const int k0 = ib * 16 + 2 * t;
    const float v0 = src[k0]     * BSCALE;
    const float v1 = src[k0 + 1] * BSCALE;
    const float v2 = src[k0 + 8] * BSCALE;
    const float v3 = src[k0 + 9] * BSCALE;
    const __half h0 = __float2half_rn(v0), h1 = __float2half_rn(v1);
    const __half h2 = __float2half_rn(v2), h3 = __float2half_rn(v3);
    uint4 o;
    {
        __half2 p;
        p = __halves2half2(h0, h1); o.x = *reinterpret_cast<uint32_t*>(&p);
        p = __halves2half2(h2, h3); o.y = *reinterpret_cast<uint32_t*>(&p);
    }
    o.z = pack_h2(v0 - __half2float(h0), v1 - __half2float(h1));
    o.w = pack_h2(v2 - __half2float(h2), v3 - __half2float(h3));
    g_bfrag[idx] = o;
}

// ============================================================================
// Fused fp16x3 GEMM + routing + mask.
// CTA: 64 tokens x 128 cols, 8 warps (2m x 4n), warp tile 32x32, m16n8k16.
// ============================================================================
__global__ __launch_bounds__(256, 2) void gemm_kernel(
    const float* __restrict__ x,
    const float* __restrict__ noise,
    float* __restrict__ out)
{
    extern __shared__ uint32_t sm[];
    const int tid  = threadIdx.x;
    const int wid  = tid >> 5;
    const int lane = tid & 31;
    const int g    = lane >> 2;
    const int t    = lane & 3;
    const int warp_m = wid & 1;
    const int warp_n = wid >> 1;
    const int blockRow = blockIdx.x * BM;
    const int arow0 = warp_m * 32;
    const int ncol0 = warp_n * 32;

    const int ar  = tid >> 2;
    const int akq = (tid & 3) * 16;
    const float* asrc = x + (size_t)(blockRow + ar) * DIMK + akq;
    const int acol = (tid & 3) * 8;

    const uint4* bbase = g_bfrag + ((ncol0 + g) * 4 + t);

    float acc[2][4][4];
    #pragma unroll
    for (int mf = 0; mf < 2; mf++)
        #pragma unroll
        for (int nf = 0; nf < 4; nf++)
            #pragma unroll
            for (int r = 0; r < 4; r++) acc[mf][nf][r] = 0.f;

    float4 aL[4];

    // ---- prologue: A chunk 0 -> smem stage 0 ----
    #pragma unroll
    for (int q = 0; q < 4; q++) aL[q] = *(const float4*)(asrc + q * 4);
    {
        uint32_t* AH = sm;
        uint32_t* AL = sm + A_SZU;
        #pragma unroll
        for (int q = 0; q < 2; q++) {
            const float f0 = aL[2*q].x,   f1 = aL[2*q].y,
                        f2 = aL[2*q].z,   f3 = aL[2*q].w,
                        f4 = aL[2*q+1].x, f5 = aL[2*q+1].y,
                        f6 = aL[2*q+1].z, f7 = aL[2*q+1].w;
            const __half h0=__float2half_rn(f0), h1=__float2half_rn(f1),
                         h2=__float2half_rn(f2), h3=__float2half_rn(f3),
                         h4=__float2half_rn(f4), h5=__float2half_rn(f5),
                         h6=__float2half_rn(f6), h7=__float2half_rn(f7);
            uint4 hv, lv;
            { __half2 p=__halves2half2(h0,h1); hv.x=*reinterpret_cast<uint32_t*>(&p);
              p=__halves2half2(h2,h3); hv.y=*reinterpret_cast<uint32_t*>(&p);
              p=__halves2half2(h4,h5); hv.z=*reinterpret_cast<uint32_t*>(&p);
              p=__halves2half2(h6,h7); hv.w=*reinterpret_cast<uint32_t*>(&p); }
            lv.x = pack_h2(f0-__half2float(h0), f1-__half2float(h1));
            lv.y = pack_h2(f2-__half2float(h2), f3-__half2float(h3));
            lv.z = pack_h2(f4-__half2float(h4), f5-__half2float(h5));
            lv.w = pack_h2(f6-__half2float(h6), f7-__half2float(h7));
            *(uint4*)(AH + ar * PAD_U + acol + q * 4) = hv;
            *(uint4*)(AL + ar * PAD_U + acol + q * 4) = lv;
        }
    }
    __syncthreads();

    uint4 Bbuf[2][4];
    #pragma unroll
    for (int nf = 0; nf < 4; nf++) Bbuf[0][nf] = bbase[nf * 32];

    for (int i = 0; i < NCHUNK; i++) {
        if (i + 1 < NCHUNK) {
            #pragma unroll
            for (int q = 0; q < 4; q++)
                aL[q] = *(const float4*)(asrc + (i + 1) * BK + q * 4);
        }

        const uint32_t* AH  = sm + (i & 1) * STAGE_U;
        const uint32_t* ALo = AH + A_SZU;
        const uint4* bi = bbase + (size_t)i * 2048;

        #pragma unroll
        for (int ks = 0; ks < 4; ks++) {
            const int cur = ks & 1, nxt = cur ^ 1;
            const uint4* bn = (ks < 3) ? (bi + (ks + 1) * 512) : (bi + 2048);
            #pragma unroll
            for (int nf = 0; nf < 4; nf++) Bbuf[nxt][nf] = bn[nf * 32];

            const int kk = ks * 8 + t;
            uint32_t Ah[2][4], Al[2][4];
            #pragma unroll
            for (int mf = 0; mf < 2; mf++) {
                const int base = (arow0 + mf * 16 + g) * PAD_U + kk;
                Ah[mf][0] = AH[base];
                Ah[mf][1] = AH[base + 8 * PAD_U];
                Ah[mf][2] = AH[base + 4];
                Ah[mf][3] = AH[base + 8 * PAD_U + 4];
                Al[mf][0] = ALo[base];
                Al[mf][1] = ALo[base + 8 * PAD_U];
                Al[mf][2] = ALo[base + 4];
                Al[mf][3] = ALo[base + 8 * PAD_U + 4];
            }

            #pragma unroll
            for (int nf = 0; nf < 4; nf++) {
                const uint32_t bh0 = Bbuf[cur][nf].x, bh1 = Bbuf[cur][nf].y;
                const uint32_t bl0 = Bbuf[cur][nf].z, bl1 = Bbuf[cur][nf].w;
                #pragma unroll
                for (int mf = 0; mf < 2; mf++) {
                    mma_f16(acc[mf][nf], Ah[mf], bh0, bh1);
                    mma_f16(acc[mf][nf], Ah[mf], bl0, bl1);
                    mma_f16(acc[mf][nf], Al[mf], bh0, bh1);
                }
            }
        }

        if (i + 1 < NCHUNK) {
            uint32_t* AHn = sm + ((i + 1) & 1) * STAGE_U;
            uint32_t* ALn = AHn + A_SZU;
            #pragma unroll
            for (int q = 0; q < 2; q++) {
                const float f0 = aL[2*q].x,   f1 = aL[2*q].y,
                            f2 = aL[2*q].z,   f3 = aL[2*q].w,
                            f4 = aL[2*q+1].x, f5 = aL[2*q+1].y,
                            f6 = aL[2*q+1].z, f7 = aL[2*q+1].w;
                const __half h0=__float2half_rn(f0), h1=__float2half_rn(f1),
                             h2=__float2half_rn(f2), h3=__float2half_rn(f3),
                             h4=__float2half_rn(f4), h5=__float2half_rn(f5),
                             h6=__float2half_rn(f6), h7=__float2half_rn(f7);
                uint4 hv, lv;
                { __half2 p=__halves2half2(h0,h1); hv.x=*reinterpret_cast<uint32_t*>(&p);
                  p=__halves2half2(h2,h3); hv.y=*reinterpret_cast<uint32_t*>(&p);
                  p=__halves2half2(h4,h5); hv.z=*reinterpret_cast<uint32_t*>(&p);
                  p=__halves2half2(h6,h7); hv.w=*reinterpret_cast<uint32_t*>(&p); }
                lv.x = pack_h2(f0-__half2float(h0), f1-__half2float(h1));
                lv.y = pack_h2(f2-__half2float(h2), f3-__half2float(h3));
                lv.z = pack_h2(f4-__half2float(h4), f5-__half2float(h5));
                lv.w = pack_h2(f6-__half2float(h6), f7-__half2float(h7));
                *(uint4*)(AHn + ar * PAD_U + acol + q * 4) = hv;
                *(uint4*)(ALn + ar * PAD_U + acol + q * 4) = lv;
            }
        }
        __syncthreads();
    }

    // ======================= fused epilogue =======================
    // Stage logits tile (64 tokens x 128 cols, unscaled) into smem.
    float* Ls = (float*)sm;
    int*   sel_s = (int*)(sm + SEL_OFF);
    #pragma unroll
    for (int mf = 0; mf < 2; mf++) {
        const int m = arow0 + mf * 16 + g;
        #pragma unroll
        for (int nf = 0; nf < 4; nf++) {
            const int n = ncol0 + nf * 8 + 2 * t;
            *(float2*)(Ls + m * L_STRIDE + n) =
                make_float2(acc[mf][nf][0] * INV_BSCALE, acc[mf][nf][1] * INV_BSCALE);
            *(float2*)(Ls + (m + 8) * L_STRIDE + n) =
                make_float2(acc[mf][nf][2] * INV_BSCALE, acc[mf][nf][3] * INV_BSCALE);
        }
    }
    __syncthreads();

    // Routing: warp w handles tokens w*8 .. w*8+7 (2 experts per lane).
    for (int tk = 0; tk < 8; tk++) {
        const int nl = wid * 8 + tk;         // local token
        const int n  = blockRow + nl;        // global token

        const float2 rv = *(const float2*)(Ls + nl * L_STRIDE + 2 * lane);
        const float2 wv = *(const float2*)(Ls + nl * L_STRIDE + 64 + 2 * lane);
        const float2 nz = *(const float2*)(noise + (size_t)n * 64 + 2 * lane);

        float rl[2], sv[2], sd[2];
        rl[0] = rv.x; rl[1] = rv.y;
        {
            const float sp0 = fmaxf(wv.x, 0.f) + log1pf(expf(-fabsf(wv.x)));
            const float sp1 = fmaxf(wv.y, 0.f) + log1pf(expf(-fabsf(wv.y)));
            sd[0] = sp0 + 0.01f;
            sd[1] = sp1 + 0.01f;
            sv[0] = fmaf(nz.x, sd[0], rl[0]);
            sv[1] = fmaf(nz.y, sd[1], rl[1]);
        }

        // top-3 via warp argmax (ties -> smaller index)
        float vtop[3]; int itop[3];
        float cur0 = sv[0], cur1 = sv[1];
        #pragma unroll
        for (int r = 0; r < 3; r++) {
            float bv; int bi;
            if (cur0 >= cur1) { bv = cur0; bi = lane * 2; }
            else              { bv = cur1; bi = lane * 2 + 1; }
            #pragma unroll
            for (int off = 16; off; off >>= 1) {
                const float ov = __shfl_xor_sync(0xffffffffu, bv, off);
                const int   oi = __shfl_xor_sync(0xffffffffu, bi, off);
                if (ov > bv || (ov == bv && oi < bi)) { bv = ov; bi = oi; }
            }
            vtop[r] = bv; itop[r] = bi;
            if ((bi >> 1) == lane) {
                if (bi & 1) cur1 = -CUDART_INF_F; else cur0 = -CUDART_INF_F;
            }
        }

        const float thr2 = vtop[1];
        const float thr3 = vtop[2];

        if (lane == 0) {
            const float a = expf(vtop[1] - vtop[0]);
            const float s = 1.f + a;
            out[OUT_RW  + n * 2 + 0] = 1.f / s;
            out[OUT_RW  + n * 2 + 1] = a / s;
            out[OUT_SEL + n * 2 + 0] = (float)itop[0];
            out[OUT_SEL + n * 2 + 1] = (float)itop[1];
            sel_s[nl * 2 + 0] = itop[0];
            sel_s[nl * 2 + 1] = itop[1];
        }

        float2 ld;
        {
            const bool in0 = sv[0] > thr3;
            const bool in1 = sv[1] > thr3;
            ld.x = normcdff((rl[0] - (in0 ? thr3 : thr2)) / sd[0]);
            ld.y = normcdff((rl[1] - (in1 ? thr3 : thr2)) / sd[1]);
        }
        *(float2*)(out + OUT_LOAD + (size_t)n * 64 + 2 * lane) = ld;
    }
    __syncthreads();

    // Mask slice: rows (e*2+j) x this CTA's 64 tokens, float4 stores.
    // thread -> row = tid>>1, 8 float4 in the (tid&1) half of the row.
    {
        const int row = tid >> 1;            // 0..127 = e*2+j
        const int e   = row >> 1;
        const int j   = row & 1;
        float* mrow = out + OUT_MASK + (size_t)row * N_TOK + blockRow + (tid & 1) * 32;
        const int nl0 = (tid & 1) * 32;
        #pragma unroll
        for (int q = 0; q < 8; q++) {
            const int nb = nl0 + q * 4;
            float4 v;
            v.x = (sel_s[(nb + 0) * 2 + j] == e) ? 1.f : 0.f;
            v.y = (sel_s[(nb + 1) * 2 + j] == e) ? 1.f : 0.f;
            v.z = (sel_s[(nb + 2) * 2 + j] == e) ? 1.f : 0.f;
            v.w = (sel_s[(nb + 3) * 2 + j] == e) ? 1.f : 0.f;
            *(float4*)(mrow + q * 4) = v;
        }
    }
}

extern "C" void kernel_launch(void* const* d_in, const int* in_sizes, int n_in,
                              void* d_out, int out_size)
{
    const float* x     = (const float*)d_in[0];
    const float* wg    = (const float*)d_in[1];
    const float* wn    = (const float*)d_in[2];
    const float* noise = (const float*)d_in[3];
    float* out = (float*)d_out;

    cudaFuncSetAttribute(gemm_kernel,
                         cudaFuncAttributeMaxDynamicSharedMemorySize, SMEM_BYTES);

    presplit_kernel<<<256, 256>>>(wg, wn);
    gemm_kernel<<<N_TOK / BM, 256, SMEM_BYTES>>>(x, noise, out);
}

// round 7
// speedup vs baseline: 2.4180x; 1.0410x over previous
#include <cuda_runtime.h>
#include <cuda_fp16.h>
#include <math.h>
#include <math_constants.h>
#include <cstdint>

#define N_TOK 16384
#define DIMK  2048
#define NOUT  128
#define BM    64
#define BK    64           // fp32 k elems per smem stage (4 x k16 blocks)
#define NCHUNK (DIMK / BK)      // 32
// A smem: packed f16x2 (hi,lo), u32 row stride 36 (conflict-free LDSM + STS.128)
#define PAD_U 36
#define A_SZU (BM * PAD_U)                  // 2304 u32
#define STAGE_U (2 * A_SZU)                 // AH + AL
#define SMEM_BYTES (2 * STAGE_U * 4)        // 36864 B  (also covers epilogue use)

#define BSCALE     512.0f                   // 2^9 weight pre-scale
#define INV_BSCALE (1.0f / 512.0f)

// epilogue smem layout (reusing mainloop buffers)
#define L_STRIDE 132
#define SEL_OFF  (64 * L_STRIDE)

// output offsets (floats)
#define OUT_RW   0
#define OUT_SEL  32768
#define OUT_MASK 65536
#define OUT_LOAD 2162688

// ---- scratch (no allocations allowed) ----
__device__ uint4 g_bfrag[128 * 128 * 4 + 2048];   // 1 MB + prefetch pad

__device__ __forceinline__ uint32_t smem_u32(const void* p) {
    uint32_t a;
    asm("{ .reg .u64 t; cvta.to.shared.u64 t, %1; cvt.u32.u64 %0, t; }"
        : "=r"(a) : "l"(p));
    return a;
}
__device__ __forceinline__ uint32_t pack_h2(float lo, float hi) {
    __half2 h = __halves2half2(__float2half_rn(lo), __float2half_rn(hi));
    return *reinterpret_cast<uint32_t*>(&h);
}
__device__ __forceinline__ void mma_f16(float* c, const uint32_t* a,
                                        uint32_t b0, uint32_t b1) {
    asm volatile(
        "mma.sync.aligned.m16n8k16.row.col.f32.f16.f16.f32 "
        "{%0,%1,%2,%3}, {%4,%5,%6,%7}, {%8,%9}, {%0,%1,%2,%3};"
        : "+f"(c[0]), "+f"(c[1]), "+f"(c[2]), "+f"(c[3])
        : "r"(a[0]), "r"(a[1]), "r"(a[2]), "r"(a[3]), "r"(b0), "r"(b1));
}
__device__ __forceinline__ void ldsm_x4(uint32_t* r, uint32_t addr) {
    asm volatile("ldmatrix.sync.aligned.m8n8.x4.shared.b16 {%0,%1,%2,%3}, [%4];"
        : "=r"(r[0]), "=r"(r[1]), "=r"(r[2]), "=r"(r[3]) : "r"(addr));
}

// ============================================================================
// Pre-split B (w_gate;w_noise), scaled by BSCALE, into fp16 hi/lo fragments.
// ============================================================================
__global__ __launch_bounds__(256) void presplit_kernel(
    const float* __restrict__ wg, const float* __restrict__ wn)
{
    const int idx = blockIdx.x * 256 + threadIdx.x;   // 0..65535
    const int t  = idx & 3;
    const int n  = (idx >> 2) & 127;
    const int ib = idx >> 9;
    const float* src = (n < 64) ? (wg + (size_t)n * DIMK)
                                : (wn + (size_t)(n - 64) * DIMK);
    const int k0 = ib * 16 + 2 * t;
    const float v0 = src[k0]     * BSCALE;
    const float v1 = src[k0 + 1] * BSCALE;
    const float v2 = src[k0 + 8] * BSCALE;
    const float v3 = src[k0 + 9] * BSCALE;
    const __half h0 = __float2half_rn(v0), h1 = __float2half_rn(v1);
    const __half h2 = __float2half_rn(v2), h3 = __float2half_rn(v3);
    uint4 o;
    {
        __half2 p;
        p = __halves2half2(h0, h1); o.x = *reinterpret_cast<uint32_t*>(&p);
        p = __halves2half2(h2, h3); o.y = *reinterpret_cast<uint32_t*>(&p);
    }
    o.z = pack_h2(v0 - __half2float(h0), v1 - __half2float(h1));
    o.w = pack_h2(v2 - __half2float(h2), v3 - __half2float(h3));
    g_bfrag[idx] = o;
}

// ============================================================================
// Fused fp16x3 GEMM + routing + mask.
// CTA: 64 tokens x 128 cols, 8 warps (2m x 4n), warp tile 32x32, m16n8k16.
// A frags via ldmatrix.x4, double-buffered across ks.
// ============================================================================
__global__ __launch_bounds__(256, 2) void gemm_kernel(
    const float* __restrict__ x,
    const float* __restrict__ noise,
    float* __restrict__ out)
{
    extern __shared__ uint32_t sm[];
    const int tid  = threadIdx.x;
    const int wid  = tid >> 5;
    const int lane = tid & 31;
    const int g    = lane >> 2;
    const int t    = lane & 3;
    const int warp_m = wid & 1;
    const int warp_n = wid >> 1;
    const int blockRow = blockIdx.x * BM;
    const int arow0 = warp_m * 32;
    const int ncol0 = warp_n * 32;

    const int ar  = tid >> 2;
    const int akq = (tid & 3) * 16;
    const float* asrc = x + (size_t)(blockRow + ar) * DIMK + akq;
    const int acol = (tid & 3) * 8;

    const uint4* bbase = g_bfrag + ((ncol0 + g) * 4 + t);

    // ldmatrix pointer for A fragments: lane -> (row, 16B column)
    const int arow_l = arow0 + ((lane >> 3) & 1) * 8 + (lane & 7);
    const uint32_t smem_b = smem_u32(sm);
    const uint32_t afrag = smem_b + (uint32_t)(arow_l * PAD_U + (lane >> 4) * 4) * 4;
    // addr(stage, lo?, mf, ks) = afrag + stage*STAGE_U*4 + lo*A_SZU*4 + mf*2304 + ks*32

    float acc[2][4][4];
    #pragma unroll
    for (int mf = 0; mf < 2; mf++)
        #pragma unroll
        for (int nf = 0; nf < 4; nf++)
            #pragma unroll
            for (int r = 0; r < 4; r++) acc[mf][nf][r] = 0.f;

    float4 aL[4];

    // ---- prologue: A chunk 0 -> smem stage 0 ----
    #pragma unroll
    for (int q = 0; q < 4; q++) aL[q] = *(const float4*)(asrc + q * 4);
    {
        uint32_t* AH = sm;
        uint32_t* AL = sm + A_SZU;
        #pragma unroll
        for (int q = 0; q < 2; q++) {
            const float f0 = aL[2*q].x,   f1 = aL[2*q].y,
                        f2 = aL[2*q].z,   f3 = aL[2*q].w,
                        f4 = aL[2*q+1].x, f5 = aL[2*q+1].y,
                        f6 = aL[2*q+1].z, f7 = aL[2*q+1].w;
            const __half h0=__float2half_rn(f0), h1=__float2half_rn(f1),
                         h2=__float2half_rn(f2), h3=__float2half_rn(f3),
                         h4=__float2half_rn(f4), h5=__float2half_rn(f5),
                         h6=__float2half_rn(f6), h7=__float2half_rn(f7);
            uint4 hv, lv;
            { __half2 p=__halves2half2(h0,h1); hv.x=*reinterpret_cast<uint32_t*>(&p);
              p=__halves2half2(h2,h3); hv.y=*reinterpret_cast<uint32_t*>(&p);
              p=__halves2half2(h4,h5); hv.z=*reinterpret_cast<uint32_t*>(&p);
              p=__halves2half2(h6,h7); hv.w=*reinterpret_cast<uint32_t*>(&p); }
            lv.x = pack_h2(f0-__half2float(h0), f1-__half2float(h1));
            lv.y = pack_h2(f2-__half2float(h2), f3-__half2float(h3));
            lv.z = pack_h2(f4-__half2float(h4), f5-__half2float(h5));
            lv.w = pack_h2(f6-__half2float(h6), f7-__half2float(h7));
            *(uint4*)(AH + ar * PAD_U + acol + q * 4) = hv;
            *(uint4*)(AL + ar * PAD_U + acol + q * 4) = lv;
        }
    }
    __syncthreads();

    uint32_t Afh[2][2][4], Afl[2][2][4];   // [buf][mf][4]
    uint4 Bbuf[2][4];
    #pragma unroll
    for (int nf = 0; nf < 4; nf++) Bbuf[0][nf] = bbase[nf * 32];
    // preload A frags for (chunk 0, ks 0)
    ldsm_x4(Afh[0][0], afrag);
    ldsm_x4(Afh[0][1], afrag + 2304);
    ldsm_x4(Afl[0][0], afrag + A_SZU * 4);
    ldsm_x4(Afl[0][1], afrag + A_SZU * 4 + 2304);

    for (int i = 0; i < NCHUNK; i++) {
        if (i + 1 < NCHUNK) {
            #pragma unroll
            for (int q = 0; q < 4; q++)
                aL[q] = *(const float4*)(asrc + (i + 1) * BK + q * 4);
        }

        const uint32_t stb = afrag + (uint32_t)(i & 1) * (STAGE_U * 4);
        const uint4* bi = bbase + (size_t)i * 2048;

        #pragma unroll
        for (int ks = 0; ks < 4; ks++) {
            const int cur = ks & 1, nxt = cur ^ 1;
            // prefetch A frags for ks+1 (same stage)
            if (ks < 3) {
                ldsm_x4(Afh[nxt][0], stb + (ks + 1) * 32);
                ldsm_x4(Afh[nxt][1], stb + 2304 + (ks + 1) * 32);
                ldsm_x4(Afl[nxt][0], stb + A_SZU * 4 + (ks + 1) * 32);
                ldsm_x4(Afl[nxt][1], stb + A_SZU * 4 + 2304 + (ks + 1) * 32);
            }
            // prefetch B frags for next ks (or next chunk's ks0)
            const uint4* bn = (ks < 3) ? (bi + (ks + 1) * 512) : (bi + 2048);
            #pragma unroll
            for (int nf = 0; nf < 4; nf++) Bbuf[nxt][nf] = bn[nf * 32];

            #pragma unroll
            for (int nf = 0; nf < 4; nf++) {
                const uint32_t bh0 = Bbuf[cur][nf].x, bh1 = Bbuf[cur][nf].y;
                const uint32_t bl0 = Bbuf[cur][nf].z, bl1 = Bbuf[cur][nf].w;
                #pragma unroll
                for (int mf = 0; mf < 2; mf++) {
                    mma_f16(acc[mf][nf], Afh[cur][mf], bh0, bh1);
                    mma_f16(acc[mf][nf], Afh[cur][mf], bl0, bl1);
                    mma_f16(acc[mf][nf], Afl[cur][mf], bh0, bh1);
                }
            }
        }

        if (i + 1 < NCHUNK) {
            uint32_t* AHn = sm + ((i + 1) & 1) * STAGE_U;
            uint32_t* ALn = AHn + A_SZU;
            #pragma unroll
            for (int q = 0; q < 2; q++) {
                const float f0 = aL[2*q].x,   f1 = aL[2*q].y,
                            f2 = aL[2*q].z,   f3 = aL[2*q].w,
                            f4 = aL[2*q+1].x, f5 = aL[2*q+1].y,
                            f6 = aL[2*q+1].z, f7 = aL[2*q+1].w;
                const __half h0=__float2half_rn(f0), h1=__float2half_rn(f1),
                             h2=__float2half_rn(f2), h3=__float2half_rn(f3),
                             h4=__float2half_rn(f4), h5=__float2half_rn(f5),
                             h6=__float2half_rn(f6), h7=__float2half_rn(f7);
                uint4 hv, lv;
                { __half2 p=__halves2half2(h0,h1); hv.x=*reinterpret_cast<uint32_t*>(&p);
                  p=__halves2half2(h2,h3); hv.y=*reinterpret_cast<uint32_t*>(&p);
                  p=__halves2half2(h4,h5); hv.z=*reinterpret_cast<uint32_t*>(&p);
                  p=__halves2half2(h6,h7); hv.w=*reinterpret_cast<uint32_t*>(&p); }
                lv.x = pack_h2(f0-__half2float(h0), f1-__half2float(h1));
                lv.y = pack_h2(f2-__half2float(h2), f3-__half2float(h3));
                lv.z = pack_h2(f4-__half2float(h4), f5-__half2float(h5));
                lv.w = pack_h2(f6-__half2float(h6), f7-__half2float(h7));
                *(uint4*)(AHn + ar * PAD_U + acol + q * 4) = hv;
                *(uint4*)(ALn + ar * PAD_U + acol + q * 4) = lv;
            }
        }
        __syncthreads();

        // preload A frags for next chunk's ks=0 (from the just-filled stage)
        if (i + 1 < NCHUNK) {
            const uint32_t nstb = afrag + (uint32_t)((i + 1) & 1) * (STAGE_U * 4);
            ldsm_x4(Afh[0][0], nstb);
            ldsm_x4(Afh[0][1], nstb + 2304);
            ldsm_x4(Afl[0][0], nstb + A_SZU * 4);
            ldsm_x4(Afl[0][1], nstb + A_SZU * 4 + 2304);
        }
    }

    // ======================= fused epilogue =======================
    float* Ls = (float*)sm;
    int*   sel_s = (int*)(sm + SEL_OFF);
    #pragma unroll
    for (int mf = 0; mf < 2; mf++) {
        const int m = arow0 + mf * 16 + g;
        #pragma unroll
        for (int nf = 0; nf < 4; nf++) {
            const int n = ncol0 + nf * 8 + 2 * t;
            *(float2*)(Ls + m * L_STRIDE + n) =
                make_float2(acc[mf][nf][0] * INV_BSCALE, acc[mf][nf][1] * INV_BSCALE);
            *(float2*)(Ls + (m + 8) * L_STRIDE + n) =
                make_float2(acc[mf][nf][2] * INV_BSCALE, acc[mf][nf][3] * INV_BSCALE);
        }
    }
    __syncthreads();

    for (int tk = 0; tk < 8; tk++) {
        const int nl = wid * 8 + tk;
        const int n  = blockRow + nl;

        const float2 rv = *(const float2*)(Ls + nl * L_STRIDE + 2 * lane);
        const float2 wv = *(const float2*)(Ls + nl * L_STRIDE + 64 + 2 * lane);
        const float2 nz = *(const float2*)(noise + (size_t)n * 64 + 2 * lane);

        float rl[2], sv[2], sd[2];
        rl[0] = rv.x; rl[1] = rv.y;
        {
            const float sp0 = fmaxf(wv.x, 0.f) + log1pf(expf(-fabsf(wv.x)));
            const float sp1 = fmaxf(wv.y, 0.f) + log1pf(expf(-fabsf(wv.y)));
            sd[0] = sp0 + 0.01f;
            sd[1] = sp1 + 0.01f;
            sv[0] = fmaf(nz.x, sd[0], rl[0]);
            sv[1] = fmaf(nz.y, sd[1], rl[1]);
        }

        float vtop[3]; int itop[3];
        float cur0 = sv[0], cur1 = sv[1];
        #pragma unroll
        for (int r = 0; r < 3; r++) {
            float bv; int bi;
            if (cur0 >= cur1) { bv = cur0; bi = lane * 2; }
            else              { bv = cur1; bi = lane * 2 + 1; }
            #pragma unroll
            for (int off = 16; off; off >>= 1) {
                const float ov = __shfl_xor_sync(0xffffffffu, bv, off);
                const int   oi = __shfl_xor_sync(0xffffffffu, bi, off);
                if (ov > bv || (ov == bv && oi < bi)) { bv = ov; bi = oi; }
            }
            vtop[r] = bv; itop[r] = bi;
            if ((bi >> 1) == lane) {
                if (bi & 1) cur1 = -CUDART_INF_F; else cur0 = -CUDART_INF_F;
            }
        }

        const float thr2 = vtop[1];
        const float thr3 = vtop[2];

        if (lane == 0) {
            const float a = expf(vtop[1] - vtop[0]);
            const float s = 1.f + a;
            out[OUT_RW  + n * 2 + 0] = 1.f / s;
            out[OUT_RW  + n * 2 + 1] = a / s;
            out[OUT_SEL + n * 2 + 0] = (float)itop[0];
            out[OUT_SEL + n * 2 + 1] = (float)itop[1];
            sel_s[nl * 2 + 0] = itop[0];
            sel_s[nl * 2 + 1] = itop[1];
        }

        float2 ld;
        {
            const bool in0 = sv[0] > thr3;
            const bool in1 = sv[1] > thr3;
            ld.x = normcdff((rl[0] - (in0 ? thr3 : thr2)) / sd[0]);
            ld.y = normcdff((rl[1] - (in1 ? thr3 : thr2)) / sd[1]);
        }
        *(float2*)(out + OUT_LOAD + (size_t)n * 64 + 2 * lane) = ld;
    }
    __syncthreads();

    {
        const int row = tid >> 1;
        const int e   = row >> 1;
        const int j   = row & 1;
        float* mrow = out + OUT_MASK + (size_t)row * N_TOK + blockRow + (tid & 1) * 32;
        const int nl0 = (tid & 1) * 32;
        #pragma unroll
        for (int q = 0; q < 8; q++) {
            const int nb = nl0 + q * 4;
            float4 v;
            v.x = (sel_s[(nb + 0) * 2 + j] == e) ? 1.f : 0.f;
            v.y = (sel_s[(nb + 1) * 2 + j] == e) ? 1.f : 0.f;
            v.z = (sel_s[(nb + 2) * 2 + j] == e) ? 1.f : 0.f;
            v.w = (sel_s[(nb + 3) * 2 + j] == e) ? 1.f : 0.f;
            *(float4*)(mrow + q * 4) = v;
        }
    }
}

extern "C" void kernel_launch(void* const* d_in, const int* in_sizes, int n_in,
                              void* d_out, int out_size)
{
    const float* x     = (const float*)d_in[0];
    const float* wg    = (const float*)d_in[1];
    const float* wn    = (const float*)d_in[2];
    const float* noise = (const float*)d_in[3];
    float* out = (float*)d_out;

    cudaFuncSetAttribute(gemm_kernel,
                         cudaFuncAttributeMaxDynamicSharedMemorySize, SMEM_BYTES);

    presplit_kernel<<<256, 256>>>(wg, wn);
    gemm_kernel<<<N_TOK / BM, 256, SMEM_BYTES>>>(x, noise, out);
}